// round 2
// baseline (speedup 1.0000x reference)
#include <cuda_runtime.h>

// VectorQuantizer: argmax_k ( W[k] . z ), emit W[argmax], index, commit loss.
// W: 131072 x 1024 f32 (512 MiB) -> pure HBM-bound stream; floor ~65us @ 8TB/s.
// Single-kernel design: per-block bests -> last-block ticket -> in-kernel epilogue.
// Output layout: [quantized_st (1024 f32), index (as f32), loss (f32)].

#define VQ_DIM   1024
#define VQ_ROWS  131072
#define ARG_BLOCKS  2048
#define ARG_THREADS 256

// Per-block packed (float_key(dot) << 32 | ~row). Overwritten every launch ->
// stale data from prior replays is harmless, no init kernel needed.
__device__ unsigned long long g_block_best[ARG_BLOCKS];
__device__ unsigned int g_done_count = 0;   // last block resets to 0 each run

// Monotonic float -> uint key: preserves ordering for all finite floats.
__device__ __forceinline__ unsigned float_key(float f) {
    unsigned u = __float_as_uint(f);
    return (u & 0x80000000u) ? ~u : (u | 0x80000000u);
}

__global__ __launch_bounds__(ARG_THREADS, 2)
void vq_kernel(const float* __restrict__ z, const float* __restrict__ W,
               float* __restrict__ out, int out_size) {
    __shared__ float zs[VQ_DIM];
    __shared__ unsigned long long red64[ARG_THREADS];
    __shared__ float redf[ARG_THREADS];
    __shared__ bool is_last;

    const int tid  = threadIdx.x;
    const int lane = tid & 31;

    // Stage z into shared (4 KB), vectorized.
    const float4* z4 = (const float4*)z;
    float4* zs4 = (float4*)zs;
    for (int i = tid; i < VQ_DIM / 4; i += ARG_THREADS)
        zs4[i] = z4[i];
    __syncthreads();

    const int gwarp  = (blockIdx.x * ARG_THREADS + tid) >> 5;
    const int nwarps = (ARG_BLOCKS * ARG_THREADS) >> 5;   // 16384 warps -> 8 rows/warp

    unsigned long long best = 0ULL;

    for (int row = gwarp; row < VQ_ROWS; row += nwarps) {
        const float4* wr = (const float4*)(W + (size_t)row * VQ_DIM);
        // All 8 LDG.128s issued up front (max MLP), then FMAs against smem z.
        float4 w0 = wr[lane +   0];
        float4 w1 = wr[lane +  32];
        float4 w2 = wr[lane +  64];
        float4 w3 = wr[lane +  96];
        float4 w4 = wr[lane + 128];
        float4 w5 = wr[lane + 160];
        float4 w6 = wr[lane + 192];
        float4 w7 = wr[lane + 224];
        float a0, a1, a2, a3;
        {
            float4 p = zs4[lane +   0]; a0  = w0.x*p.x + w0.y*p.y + w0.z*p.z + w0.w*p.w;
        }
        { float4 p = zs4[lane +  32]; a1  = w1.x*p.x + w1.y*p.y + w1.z*p.z + w1.w*p.w; }
        { float4 p = zs4[lane +  64]; a2  = w2.x*p.x + w2.y*p.y + w2.z*p.z + w2.w*p.w; }
        { float4 p = zs4[lane +  96]; a3  = w3.x*p.x + w3.y*p.y + w3.z*p.z + w3.w*p.w; }
        { float4 p = zs4[lane + 128]; a0 += w4.x*p.x + w4.y*p.y + w4.z*p.z + w4.w*p.w; }
        { float4 p = zs4[lane + 160]; a1 += w5.x*p.x + w5.y*p.y + w5.z*p.z + w5.w*p.w; }
        { float4 p = zs4[lane + 192]; a2 += w6.x*p.x + w6.y*p.y + w6.z*p.z + w6.w*p.w; }
        { float4 p = zs4[lane + 224]; a3 += w7.x*p.x + w7.y*p.y + w7.z*p.z + w7.w*p.w; }
        float dot = (a0 + a1) + (a2 + a3);

        #pragma unroll
        for (int off = 16; off; off >>= 1)
            dot += __shfl_xor_sync(0xffffffffu, dot, off);

        if (lane == 0) {
            // ~row in low bits: ties resolve to SMALLEST row (jnp.argmax semantics).
            unsigned long long p =
                ((unsigned long long)float_key(dot) << 32) |
                (unsigned long long)(0xFFFFFFFFu - (unsigned)row);
            if (p > best) best = p;
        }
    }

    // Block reduce the 8 warp-leader bests via shared tree.
    red64[tid] = (lane == 0) ? best : 0ULL;
    __syncthreads();
    #pragma unroll
    for (int o = ARG_THREADS / 2; o >= 32; o >>= 1) {
        if (tid < o) { unsigned long long v = red64[tid + o]; if (v > red64[tid]) red64[tid] = v; }
        __syncthreads();
    }
    if (tid == 0) {
        unsigned long long v = red64[0];
        #pragma unroll
        for (int i = 1; i < 32; i += 32) {}  // red64[0..31] already folded above except within-warp
        // fold remaining 32 entries serially-in-warp is gone; red64[0] holds max of [0..31]? No:
        // loop above stopped at o=32, so red64[0..31] each hold a partial. Fold them here.
        for (int i = 1; i < 32; i++) { unsigned long long t = red64[i]; if (t > v) v = t; }
        g_block_best[blockIdx.x] = v;
    }

    // Last-block ticket.
    if (tid == 0) {
        __threadfence();
        unsigned t = atomicAdd(&g_done_count, 1u);
        is_last = (t == ARG_BLOCKS - 1);
    }
    __syncthreads();
    if (!is_last) return;

    // ---- Epilogue in the last block ----
    unsigned long long b = 0ULL;
    for (int i = tid; i < ARG_BLOCKS; i += ARG_THREADS) {
        unsigned long long v = g_block_best[i];
        if (v > b) b = v;
    }
    red64[tid] = b;
    __syncthreads();
    #pragma unroll
    for (int o = ARG_THREADS / 2; o; o >>= 1) {
        if (tid < o) { unsigned long long v = red64[tid + o]; if (v > red64[tid]) red64[tid] = v; }
        __syncthreads();
    }
    const unsigned row = 0xFFFFFFFFu - (unsigned)(red64[0] & 0xFFFFFFFFull);
    const float* q = W + (size_t)row * VQ_DIM;

    float s = 0.f;
    for (int i = tid; i < VQ_DIM; i += ARG_THREADS) {
        float qi = q[i];
        float d  = zs[i] - qi;
        s += d * d;
        if (i < out_size) out[i] = qi;
    }
    redf[tid] = s;
    __syncthreads();
    #pragma unroll
    for (int o = ARG_THREADS / 2; o; o >>= 1) {
        if (tid < o) redf[tid] += redf[tid + o];
        __syncthreads();
    }
    if (tid == 0) {
        if (out_size >= VQ_DIM + 1) out[VQ_DIM]     = (float)row;
        if (out_size >= VQ_DIM + 2) out[VQ_DIM + 1] = 0.25f * redf[0] / (float)VQ_DIM;
        g_done_count = 0;  // reset for next graph replay
    }
}

extern "C" void kernel_launch(void* const* d_in, const int* in_sizes, int n_in,
                              void* d_out, int out_size) {
    const float* z = (const float*)d_in[0];
    const float* W = (const float*)d_in[1];
    if (n_in >= 2 && in_sizes[0] != VQ_DIM && in_sizes[1] == VQ_DIM) {
        z = (const float*)d_in[1];
        W = (const float*)d_in[0];
    }
    vq_kernel<<<ARG_BLOCKS, ARG_THREADS>>>(z, W, (float*)d_out, out_size);
}

// round 3
// speedup vs baseline: 1.0850x; 1.0850x over previous
#include <cuda_runtime.h>

// VectorQuantizer: argmax_k ( W[k] . z ), emit W[argmax], index, commit loss.
// W: 131072 x 1024 f32 (512 MiB) -> pure HBM stream; floor ~65us @ 8 TB/s.
// Two launches: persistent streaming argmax (reg-lean, occ=4 CTA/SM) writing
// per-block slots (no atomics, no init), then a tiny finalize kernel.

#define VQ_DIM   1024
#define VQ_ROWS  131072
#define ARG_BLOCKS  592          // 148 SMs x 4 CTAs -> single wave, persistent
#define ARG_THREADS 256
#define N_WARPS_TOT (ARG_BLOCKS * ARG_THREADS / 32)

// Per-block packed (float_key(dot) << 32 | ~row). Overwritten every launch.
__device__ unsigned long long g_block_best[ARG_BLOCKS];

// Monotonic float -> uint key: preserves ordering for all finite floats.
__device__ __forceinline__ unsigned float_key(float f) {
    unsigned u = __float_as_uint(f);
    return (u & 0x80000000u) ? ~u : (u | 0x80000000u);
}

__global__ __launch_bounds__(ARG_THREADS, 4)   // cap regs at 64 -> 32 warps/SM
void vq_argmax_kernel(const float* __restrict__ z, const float* __restrict__ W) {
    __shared__ float zs[VQ_DIM];
    __shared__ unsigned long long red64[ARG_THREADS / 32];

    const int tid  = threadIdx.x;
    const int lane = tid & 31;
    const int wwid = tid >> 5;

    // Stage z into shared (4 KB), vectorized.
    const float4* z4 = (const float4*)z;
    float4* zs4 = (float4*)zs;
    for (int i = tid; i < VQ_DIM / 4; i += ARG_THREADS)
        zs4[i] = z4[i];
    __syncthreads();

    const int gwarp = (blockIdx.x * ARG_THREADS + tid) >> 5;

    unsigned long long best = 0ULL;

    for (int row = gwarp; row < VQ_ROWS; row += N_WARPS_TOT) {
        const float4* wr = (const float4*)(W + (size_t)row * VQ_DIM);
        // All 8 LDG.128s issued up front (max per-warp MLP), streaming hint.
        float4 w0 = __ldcs(wr + lane +   0);
        float4 w1 = __ldcs(wr + lane +  32);
        float4 w2 = __ldcs(wr + lane +  64);
        float4 w3 = __ldcs(wr + lane +  96);
        float4 w4 = __ldcs(wr + lane + 128);
        float4 w5 = __ldcs(wr + lane + 160);
        float4 w6 = __ldcs(wr + lane + 192);
        float4 w7 = __ldcs(wr + lane + 224);
        float a0, a1, a2, a3;
        { float4 p = zs4[lane +   0]; a0  = w0.x*p.x + w0.y*p.y + w0.z*p.z + w0.w*p.w; }
        { float4 p = zs4[lane +  32]; a1  = w1.x*p.x + w1.y*p.y + w1.z*p.z + w1.w*p.w; }
        { float4 p = zs4[lane +  64]; a2  = w2.x*p.x + w2.y*p.y + w2.z*p.z + w2.w*p.w; }
        { float4 p = zs4[lane +  96]; a3  = w3.x*p.x + w3.y*p.y + w3.z*p.z + w3.w*p.w; }
        { float4 p = zs4[lane + 128]; a0 += w4.x*p.x + w4.y*p.y + w4.z*p.z + w4.w*p.w; }
        { float4 p = zs4[lane + 160]; a1 += w5.x*p.x + w5.y*p.y + w5.z*p.z + w5.w*p.w; }
        { float4 p = zs4[lane + 192]; a2 += w6.x*p.x + w6.y*p.y + w6.z*p.z + w6.w*p.w; }
        { float4 p = zs4[lane + 224]; a3 += w7.x*p.x + w7.y*p.y + w7.z*p.z + w7.w*p.w; }
        float dot = (a0 + a1) + (a2 + a3);

        #pragma unroll
        for (int off = 16; off; off >>= 1)
            dot += __shfl_xor_sync(0xffffffffu, dot, off);

        // ~row in low bits: ties resolve to SMALLEST row (jnp.argmax semantics).
        unsigned long long p =
            ((unsigned long long)float_key(dot) << 32) |
            (unsigned long long)(0xFFFFFFFFu - (unsigned)row);
        if (p > best) best = p;
    }

    // One value per warp -> 8-entry smem max -> slot store.
    if (lane == 0) red64[wwid] = best;
    __syncthreads();
    if (tid == 0) {
        unsigned long long v = red64[0];
        #pragma unroll
        for (int i = 1; i < ARG_THREADS / 32; i++)
            if (red64[i] > v) v = red64[i];
        g_block_best[blockIdx.x] = v;
    }
}

__global__ __launch_bounds__(256)
void vq_finalize_kernel(const float* __restrict__ z,
                        const float* __restrict__ W,
                        float* __restrict__ out, int out_size) {
    __shared__ unsigned long long red64[256];
    __shared__ float redf[256];
    const int tid = threadIdx.x;

    unsigned long long b = 0ULL;
    for (int i = tid; i < ARG_BLOCKS; i += 256) {
        unsigned long long v = g_block_best[i];
        if (v > b) b = v;
    }
    red64[tid] = b;
    __syncthreads();
    #pragma unroll
    for (int o = 128; o; o >>= 1) {
        if (tid < o) { unsigned long long v = red64[tid + o]; if (v > red64[tid]) red64[tid] = v; }
        __syncthreads();
    }
    const unsigned row = 0xFFFFFFFFu - (unsigned)(red64[0] & 0xFFFFFFFFull);
    const float* q = W + (size_t)row * VQ_DIM;

    float s = 0.f;
    for (int i = tid; i < VQ_DIM; i += 256) {
        float qi = q[i];
        float d  = z[i] - qi;
        s += d * d;
        if (i < out_size) out[i] = qi;   // quantized_st == quantized numerically
    }
    redf[tid] = s;
    __syncthreads();
    #pragma unroll
    for (int o = 128; o; o >>= 1) {
        if (tid < o) redf[tid] += redf[tid + o];
        __syncthreads();
    }
    if (tid == 0) {
        if (out_size >= VQ_DIM + 1) out[VQ_DIM]     = (float)row;
        if (out_size >= VQ_DIM + 2) out[VQ_DIM + 1] = 0.25f * redf[0] / (float)VQ_DIM;
    }
}

extern "C" void kernel_launch(void* const* d_in, const int* in_sizes, int n_in,
                              void* d_out, int out_size) {
    const float* z = (const float*)d_in[0];
    const float* W = (const float*)d_in[1];
    if (n_in >= 2 && in_sizes[0] != VQ_DIM && in_sizes[1] == VQ_DIM) {
        z = (const float*)d_in[1];
        W = (const float*)d_in[0];
    }
    vq_argmax_kernel<<<ARG_BLOCKS, ARG_THREADS>>>(z, W);
    vq_finalize_kernel<<<1, 256>>>(z, W, (float*)d_out, out_size);
}